// round 14
// baseline (speedup 1.0000x reference)
#include <cuda_runtime.h>
#include <cuda_fp16.h>

#define LRELU_SLOPE 0.3f
#define BN_EPS 1e-5f
#define LOG2E 1.4426950408889634f

// Scratch: [t][b][c][h][w] : 4 x 16 x 64 x 16 x 512 floats = 134 MB
__device__ float g_qkvp[4u * 16u * 64u * 16u * 512u];
// Prepacked fp16 conv weight A-fragments: [ct 16][ks 10][lane 32] uint4
__device__ uint4 g_whf[16 * 10 * 32];
// Prepacked fp16 V fragments (pi-permuted pairs): [bc 1024][4096] half2 words
__device__ unsigned g_vh[1024u * 4096u];

__device__ __forceinline__ float to_tf32(float x) {
    unsigned u;
    asm("cvt.rna.tf32.f32 %0, %1;" : "=r"(u) : "f"(x));
    return __uint_as_float(u);
}
__device__ __forceinline__ float ex2(float x) {
    float y;
    asm("ex2.approx.f32 %0, %1;" : "=f"(y) : "f"(x));
    return y;
}
// D(16x8) += A(16x8,row) * B(8x8,col), tf32 inputs, fp32 accum
__device__ __forceinline__ void mma8(float* c, const unsigned* a, unsigned b0, unsigned b1) {
    asm volatile(
        "mma.sync.aligned.m16n8k8.row.col.f32.tf32.tf32.f32 "
        "{%0,%1,%2,%3}, {%4,%5,%6,%7}, {%8,%9}, {%0,%1,%2,%3};"
        : "+f"(c[0]), "+f"(c[1]), "+f"(c[2]), "+f"(c[3])
        : "r"(a[0]), "r"(a[1]), "r"(a[2]), "r"(a[3]), "r"(b0), "r"(b1));
}
// D(16x8) += A(16x16,row,f16) * B(16x8,col,f16), fp32 accum
__device__ __forceinline__ void mma16h(float* c, const unsigned* a, unsigned b0, unsigned b1) {
    asm volatile(
        "mma.sync.aligned.m16n8k16.row.col.f32.f16.f16.f32 "
        "{%0,%1,%2,%3}, {%4,%5,%6,%7}, {%8,%9}, {%0,%1,%2,%3};"
        : "+f"(c[0]), "+f"(c[1]), "+f"(c[2]), "+f"(c[3])
        : "r"(a[0]), "r"(a[1]), "r"(a[2]), "r"(a[3]), "r"(b0), "r"(b1));
}
__device__ __forceinline__ unsigned h2pack(float lo, float hi) {
    __half2 h = __floats2half2_rn(lo, hi);
    return *(unsigned*)&h;
}
// fragment-plane index (float2 units)
__device__ __forceinline__ int Fidx(int w, int q) {
    return (w << 2) + (q ^ ((w >> 2) & 3));
}

struct ConvParams {
    const float* x;
    const float* w[4];
    const float* gamma[4];
    const float* beta[4];
    const float* mean[4];
    const float* var[4];
};

// ---------------------------------------------------------------------------
// Prepack: fold BN scale into W, fp16-round, store m16n8k16 A-fragments.
// (unchanged from R12)
// ---------------------------------------------------------------------------
__global__ void prepack_kernel(ConvParams P) {
    int idx = blockIdx.x * 256 + threadIdx.x;
    if (idx >= 16 * 10 * 32) return;
    int lane = idx & 31;
    int ks   = (idx >> 5) % 10;
    int ct   = idx / 320;
    int g = lane >> 2, q = lane & 3;
    int tap = ks >> 1, cb = (ks & 1) * 16;
    int co0 = ct * 16 + g, co1 = co0 + 8;
    int t0 = co0 >> 6, c0 = co0 & 63;
    int t1 = co1 >> 6, c1 = co1 & 63;
    float sc0 = P.gamma[t0][c0] * rsqrtf(P.var[t0][c0] + BN_EPS);
    float sc1 = P.gamma[t1][c1] * rsqrtf(P.var[t1][c1] + BN_EPS);
    int ciA = cb + 2 * q, ciB = cb + 2 * q + 8;
    uint4 v;
    v.x = h2pack(P.w[t0][(c0 * 32 + ciA) * 5 + tap] * sc0,
                 P.w[t0][(c0 * 32 + ciA + 1) * 5 + tap] * sc0);
    v.y = h2pack(P.w[t1][(c1 * 32 + ciA) * 5 + tap] * sc1,
                 P.w[t1][(c1 * 32 + ciA + 1) * 5 + tap] * sc1);
    v.z = h2pack(P.w[t0][(c0 * 32 + ciB) * 5 + tap] * sc0,
                 P.w[t0][(c0 * 32 + ciB + 1) * 5 + tap] * sc0);
    v.w = h2pack(P.w[t1][(c1 * 32 + ciB) * 5 + tap] * sc1,
                 P.w[t1][(c1 * 32 + ciB + 1) * 5 + tap] * sc1);
    g_whf[idx] = v;
}

// ---------------------------------------------------------------------------
// Conv via fp16 mma m16n8k16. grid (4,16,16); 512 threads = 16 warps.
// (unchanged from R12)
// ---------------------------------------------------------------------------
__global__ void __launch_bounds__(512, 1) conv_mma_kernel(ConvParams P) {
    extern __shared__ float sm[];
    uint2* Xh  = (uint2*)sm;                   // 1088 uint2 = 8704 B
    uint4* Wfs = (uint4*)(Xh + 1088);          // 5120 uint4 = 81920 B

    const int nc = blockIdx.x;
    const int h  = blockIdx.y;
    const int b  = blockIdx.z;
    const int tid = threadIdx.x;
    const int lane = tid & 31, wp = tid >> 5;
    const int g = lane >> 2, q = lane & 3;
    const int w0 = nc * 128;

#pragma unroll
    for (int i = 0; i < 10; i++)
        Wfs[i * 512 + tid] = g_whf[i * 512 + tid];

    for (int i = tid; i < 1088; i += 512) {
        int q2 = i & 3, oc = i >> 2;
        int o = oc / 136, col = oc - o * 136;
        int wg = w0 - 2 + col;
        uint2 word = make_uint2(0u, 0u);
        if (wg >= 0 && wg < 512) {
            int ciA = 16 * o + 2 * q2;
            const float* xp = P.x + (size_t)((b * 32 + ciA) * 16 + h) * 512 + wg;
            const size_t rs = 16 * 512;
            word.x = h2pack(xp[0], xp[rs]);
            word.y = h2pack(xp[8 * rs], xp[9 * rs]);
        }
        Xh[i] = word;
    }
    __syncthreads();

    float O[16][4];
#pragma unroll
    for (int j = 0; j < 16; j++)
#pragma unroll
        for (int u = 0; u < 4; u++) O[j][u] = 0.0f;

#pragma unroll
    for (int ks = 0; ks < 10; ks++) {
        int tap = ks >> 1, o = ks & 1;
        uint4 A = Wfs[(wp * 10 + ks) * 32 + lane];
        unsigned a[4] = { A.x, A.y, A.z, A.w };
        const uint2* bp = Xh + ((o * 136) + g + tap) * 4 + q;
#pragma unroll
        for (int j = 0; j < 16; j++) {
            uint2 bb = bp[j * 32];
            mma16h(O[j], a, bb.x, bb.y);
        }
    }

    const int co0 = wp * 16 + g;
    const int t0 = co0 >> 6, c0 = co0 & 63;
    const int c1 = (co0 + 8) & 63;
    float sA = P.gamma[t0][c0] * rsqrtf(P.var[t0][c0] + BN_EPS);
    float shift0 = P.beta[t0][c0] - P.mean[t0][c0] * sA;
    float sB = P.gamma[t0][c1] * rsqrtf(P.var[t0][c1] + BN_EPS);
    float shift1 = P.beta[t0][c1] - P.mean[t0][c1] * sB;

    float* r0 = g_qkvp + (size_t)(((t0 * 16 + b) * 64 + c0) * 16 + h) * 512 + w0 + 2 * q;
    float* r1 = g_qkvp + (size_t)(((t0 * 16 + b) * 64 + c1) * 16 + h) * 512 + w0 + 2 * q;
#pragma unroll
    for (int j = 0; j < 16; j++) {
        float v0 = O[j][0] + shift0, v1 = O[j][1] + shift0;
        float v2 = O[j][2] + shift1, v3 = O[j][3] + shift1;
        v0 = (v0 >= 0.0f) ? v0 : LRELU_SLOPE * v0;
        v1 = (v1 >= 0.0f) ? v1 : LRELU_SLOPE * v1;
        v2 = (v2 >= 0.0f) ? v2 : LRELU_SLOPE * v2;
        v3 = (v3 >= 0.0f) ? v3 : LRELU_SLOPE * v3;
        *(float2*)(r0 + j * 8) = make_float2(v0, v1);
        *(float2*)(r1 + j * 8) = make_float2(v2, v3);
    }
}

// ---------------------------------------------------------------------------
// V pack: g_qkvp V-plane -> pi-permuted fp16 fragment words in global.
// word (bc; kb,hh,qs,oh) = (V[hh][kb*16+oh*8+qs], V[hh][kb*16+oh*8+qs+4])
// at index bc*4096 + kb*128 + hh*8 + qs*2 + oh.  (same layout R12 used in smem)
// ---------------------------------------------------------------------------
__global__ void vpack_kernel() {
    int gid = blockIdx.x * 256 + threadIdx.x;     // 1024*4096 words
    int bc = gid >> 12;
    int r  = gid & 4095;
    int hh = r >> 8;
    int cw = r & 255;
    int qs = cw & 3, oh = (cw >> 2) & 1, kb = cw >> 3;
    int cc = kb * 16 + oh * 8 + qs;
    const float* vg = g_qkvp + (size_t)(2 * 1024 + bc) * 8192;
    g_vh[((size_t)bc << 12) + kb * 128 + hh * 8 + qs * 2 + oh] =
        h2pack(vg[hh * 512 + cc], vg[hh * 512 + cc + 4]);
}

// ---------------------------------------------------------------------------
// Attention per (b,c): R12 math, 256-thread CTAs, 32-row blocks, 2 CTAs/SM.
// Phase A tf32 mma (warp tile m32 x n64), max-free exp2 softmax,
// Phase B f16 mma with pi-permutation; V frags read from global (L1-resident).
// 1024 CTAs, 256 threads, 99584 B smem.
// ---------------------------------------------------------------------------
__global__ void __launch_bounds__(256, 2) attn_kernel(float* __restrict__ out) {
    extern __shared__ float sm[];
    float2*   Qf2 = (float2*)sm;                  // 4096 f2 (tf32 frag pairs)
    float2*   Kf2 = Qf2 + 4096;                   // 4096 f2
    unsigned* Ph  = (unsigned*)(Kf2 + 4096);      // 8192 half2 words (32 rows)
    float*    redP = (float*)(Ph + 8192);         // 32*9
    float*    redI = redP + 32 * 9;               // 32

    const int bc   = blockIdx.x;
    const int tid  = threadIdx.x;
    const int lane = tid & 31, wp = tid >> 5;     // wp 0..7
    const int g = lane >> 2, q = lane & 3;

    // ---- Staging Q, K (R12 pattern, 2 columns per thread) ----
    {
        const float* qg = g_qkvp + (size_t)(0 * 1024 + bc) * 8192;
        const float* kg = g_qkvp + (size_t)(1 * 1024 + bc) * 8192;
#pragma unroll
        for (int wi = 0; wi < 2; wi++) {
            const int w = tid + wi * 256;
#pragma unroll
            for (int j = 0; j < 8; j++) {
                int ks = j >> 2, qq = j & 3;
                int h0 = ks * 8 + qq;
                float a0 = qg[h0 * 512 + w] * LOG2E;
                float a1 = qg[(h0 + 4) * 512 + w] * LOG2E;
                Qf2[ks * 2048 + Fidx(w, qq)] = make_float2(to_tf32(a0), to_tf32(a1));
                float k0 = kg[h0 * 512 + w];
                float k1 = kg[(h0 + 4) * 512 + w];
                Kf2[ks * 2048 + Fidx(w, qq)] = make_float2(to_tf32(k0), to_tf32(k1));
            }
        }
    }
    __syncthreads();

    const int nbA   = wp * 64;                 // warp's 64-col stripe (A and B)
    const int rbase = (g & 3) + 8 * (g >> 2);
    const int qs    = g & 3, hb = g >> 2;

    const int gbA = nbA + g;
    const float2* kE = Kf2 + gbA * 4 + (q ^ ((gbA >> 2) & 3));
    const float2* kO = Kf2 + (gbA + 8) * 4 + (q ^ (((gbA + 8) >> 2) & 3));

    const unsigned* Vg = g_vh + ((size_t)bc << 12);

    float O[8][4];
#pragma unroll
    for (int t = 0; t < 8; t++)
#pragma unroll
        for (int u = 0; u < 4; u++) O[t][u] = 0.0f;

    for (int blk = 0; blk < 16; blk++) {
        // ---- Phase A: logits, warp tile = 32 rows x 64 cols ----
        float L[2][8][4];
#pragma unroll
        for (int mt = 0; mt < 2; mt++)
#pragma unroll
            for (int j = 0; j < 8; j++)
#pragma unroll
                for (int u = 0; u < 4; u++) L[mt][j][u] = 0.0f;

#pragma unroll
        for (int ks = 0; ks < 2; ks++) {
            // Q fragments for both 16-row tiles (hoisted per ks)
            unsigned a0[4], a1[4];
            {
                int W1 = blk * 32 + rbase;
                float2 p0 = Qf2[ks * 2048 + Fidx(W1, q)];
                float2 p1 = Qf2[ks * 2048 + Fidx(W1 + 4, q)];
                a0[0] = __float_as_uint(p0.x); a0[1] = __float_as_uint(p1.x);
                a0[2] = __float_as_uint(p0.y); a0[3] = __float_as_uint(p1.y);
                float2 p2 = Qf2[ks * 2048 + Fidx(W1 + 16, q)];
                float2 p3 = Qf2[ks * 2048 + Fidx(W1 + 20, q)];
                a1[0] = __float_as_uint(p2.x); a1[1] = __float_as_uint(p3.x);
                a1[2] = __float_as_uint(p2.y); a1[3] = __float_as_uint(p3.y);
            }
#pragma unroll
            for (int t2 = 0; t2 < 4; t2++) {
                float2 bE = kE[ks * 2048 + t2 * 64];
                float2 bO = kO[ks * 2048 + t2 * 64];
                unsigned bx0 = __float_as_uint(bE.x), by0 = __float_as_uint(bE.y);
                unsigned bx1 = __float_as_uint(bO.x), by1 = __float_as_uint(bO.y);
                mma8(L[0][2 * t2],     a0, bx0, by0);
                mma8(L[0][2 * t2 + 1], a0, bx1, by1);
                mma8(L[1][2 * t2],     a1, bx0, by0);
                mma8(L[1][2 * t2 + 1], a1, bx1, by1);
            }
        }

        // ---- exp2 + 2-stage row-sum reduction ----
#pragma unroll
        for (int mt = 0; mt < 2; mt++) {
            float pa = 0.0f, pb = 0.0f;
#pragma unroll
            for (int j = 0; j < 8; j++) {
                float e0 = ex2(L[mt][j][0]); L[mt][j][0] = e0;
                float e1 = ex2(L[mt][j][1]); L[mt][j][1] = e1; pa += e0 + e1;
                float e2 = ex2(L[mt][j][2]); L[mt][j][2] = e2;
                float e3 = ex2(L[mt][j][3]); L[mt][j][3] = e3; pb += e2 + e3;
            }
            pa += __shfl_xor_sync(0xffffffffu, pa, 1);
            pa += __shfl_xor_sync(0xffffffffu, pa, 2);
            pb += __shfl_xor_sync(0xffffffffu, pb, 1);
            pb += __shfl_xor_sync(0xffffffffu, pb, 2);
            if (q == 0) {
                redP[(mt * 16 + rbase) * 9 + wp]     = pa;
                redP[(mt * 16 + rbase + 4) * 9 + wp] = pb;
            }
        }
        __syncthreads();
        {
            int row = tid >> 3, jj = tid & 7;
            float s = redP[row * 9 + jj];
            s += __shfl_xor_sync(0xffffffffu, s, 1);
            s += __shfl_xor_sync(0xffffffffu, s, 2);
            s += __shfl_xor_sync(0xffffffffu, s, 4);
            if (jj == 0) redI[row] = __fdividef(1.0f, s);
        }
        __syncthreads();

        // ---- P store as half2 (rows r, r+4 packed; pi-layout; R12 formula) ----
#pragma unroll
        for (int mt = 0; mt < 2; mt++) {
            float invA = redI[mt * 16 + rbase];
            float invB = redI[mt * 16 + rbase + 4];
#pragma unroll
            for (int j = 0; j < 8; j++) {
                int col = nbA + j * 8 + 2 * q;
                int swz = (qs * 2 + hb) ^ (col & 4);
                Ph[(mt * 512 + col) * 8 + swz] =
                    h2pack(L[mt][j][0] * invA, L[mt][j][2] * invB);
                Ph[(mt * 512 + col + 1) * 8 + swz] =
                    h2pack(L[mt][j][1] * invA, L[mt][j][3] * invB);
            }
        }
        __syncthreads();

        // ---- Phase B: O += V @ P, f16 m16n8k16 (V frags from global) ----
#pragma unroll
        for (int ks = 0; ks < 2; ks++) {
            int kbV = blk * 2 + ks;
            uint2 va = *(const uint2*)(Vg + ((kbV * 16 + g) * 4 + q) * 2);
            uint2 vb = *(const uint2*)(Vg + ((kbV * 16 + g + 8) * 4 + q) * 2);
            unsigned a[4] = { va.x, vb.x, va.y, vb.y };
#pragma unroll
            for (int nt = 0; nt < 8; nt++) {
                int col = nbA + nt * 8 + g;
                uint2 bb = *(const uint2*)(Ph + (ks * 512 + col) * 8 + ((q * 2) ^ (col & 4)));
                mma16h(O[nt], a, bb.x, bb.y);
            }
        }
        __syncthreads();
    }

    // ---- epilogue: + PE, store ----
    const float* pe = g_qkvp + (size_t)(3 * 1024 + bc) * 8192;
    float* dst = out + (size_t)bc * 8192;
#pragma unroll
    for (int t = 0; t < 8; t++) {
        int col = nbA + t * 8 + 2 * q;
        float2 pA = *(const float2*)(pe + g * 512 + col);
        float2 pB = *(const float2*)(pe + (g + 8) * 512 + col);
        *(float2*)(dst + g * 512 + col) =
            make_float2(O[t][0] + pA.x, O[t][1] + pA.y);
        *(float2*)(dst + (g + 8) * 512 + col) =
            make_float2(O[t][2] + pB.x, O[t][3] + pB.y);
    }
}

// ---------------------------------------------------------------------------
extern "C" void kernel_launch(void* const* d_in, const int* in_sizes, int n_in,
                              void* d_out, int out_size) {
    (void)in_sizes; (void)n_in; (void)out_size;

    ConvParams P;
    P.x = (const float*)d_in[0];
    for (int i = 0; i < 4; i++) {
        P.w[i]     = (const float*)d_in[1 + i * 5 + 0];
        P.gamma[i] = (const float*)d_in[1 + i * 5 + 1];
        P.beta[i]  = (const float*)d_in[1 + i * 5 + 2];
        P.mean[i]  = (const float*)d_in[1 + i * 5 + 3];
        P.var[i]   = (const float*)d_in[1 + i * 5 + 4];
    }

    const int CONV_SMEM = 1088 * 8 + 16 * 10 * 32 * 16;                    // 90624 B
    const int ATTN_SMEM = 4096 * 8 * 2 + 8192 * 4 + (32 * 9) * 4 + 32 * 4; // 99584 B
    cudaFuncSetAttribute(conv_mma_kernel, cudaFuncAttributeMaxDynamicSharedMemorySize, CONV_SMEM);
    cudaFuncSetAttribute(attn_kernel, cudaFuncAttributeMaxDynamicSharedMemorySize, ATTN_SMEM);

    prepack_kernel<<<20, 256>>>(P);
    conv_mma_kernel<<<dim3(4, 16, 16), 512, CONV_SMEM>>>(P);
    vpack_kernel<<<16384, 256>>>();
    attn_kernel<<<1024, 256, ATTN_SMEM>>>((float*)d_out);
}

// round 15
// speedup vs baseline: 1.4931x; 1.4931x over previous
#include <cuda_runtime.h>
#include <cuda_fp16.h>

#define LRELU_SLOPE 0.3f
#define BN_EPS 1e-5f
#define LOG2E 1.4426950408889634f

// Scratch: [t][b][c][h][w] : 4 x 16 x 64 x 16 x 512 floats = 134 MB
__device__ float g_qkvp[4u * 16u * 64u * 16u * 512u];
// Prepacked fp16 conv weight A-fragments: [ct 16][ks 10][lane 32] uint4
__device__ uint4 g_whf[16 * 10 * 32];

__device__ __forceinline__ float to_tf32(float x) {
    unsigned u;
    asm("cvt.rna.tf32.f32 %0, %1;" : "=r"(u) : "f"(x));
    return __uint_as_float(u);
}
__device__ __forceinline__ float ex2(float x) {
    float y;
    asm("ex2.approx.f32 %0, %1;" : "=f"(y) : "f"(x));
    return y;
}
// D(16x8) += A(16x8,row) * B(8x8,col), tf32 inputs, fp32 accum
__device__ __forceinline__ void mma8(float* c, const unsigned* a, unsigned b0, unsigned b1) {
    asm volatile(
        "mma.sync.aligned.m16n8k8.row.col.f32.tf32.tf32.f32 "
        "{%0,%1,%2,%3}, {%4,%5,%6,%7}, {%8,%9}, {%0,%1,%2,%3};"
        : "+f"(c[0]), "+f"(c[1]), "+f"(c[2]), "+f"(c[3])
        : "r"(a[0]), "r"(a[1]), "r"(a[2]), "r"(a[3]), "r"(b0), "r"(b1));
}
// D(16x8) += A(16x16,row,f16) * B(16x8,col,f16), fp32 accum
__device__ __forceinline__ void mma16h(float* c, const unsigned* a, unsigned b0, unsigned b1) {
    asm volatile(
        "mma.sync.aligned.m16n8k16.row.col.f32.f16.f16.f32 "
        "{%0,%1,%2,%3}, {%4,%5,%6,%7}, {%8,%9}, {%0,%1,%2,%3};"
        : "+f"(c[0]), "+f"(c[1]), "+f"(c[2]), "+f"(c[3])
        : "r"(a[0]), "r"(a[1]), "r"(a[2]), "r"(a[3]), "r"(b0), "r"(b1));
}
__device__ __forceinline__ unsigned h2pack(float lo, float hi) {
    __half2 h = __floats2half2_rn(lo, hi);
    return *(unsigned*)&h;
}
// fragment-plane index (float2 units)
__device__ __forceinline__ int Fidx(int w, int q) {
    return (w << 2) + (q ^ ((w >> 2) & 3));
}

struct ConvParams {
    const float* x;
    const float* w[4];
    const float* gamma[4];
    const float* beta[4];
    const float* mean[4];
    const float* var[4];
};

// ---------------------------------------------------------------------------
// Prepack: fold BN scale into W, fp16-round, store m16n8k16 A-fragments.
// ---------------------------------------------------------------------------
__global__ void prepack_kernel(ConvParams P) {
    int idx = blockIdx.x * 256 + threadIdx.x;
    if (idx >= 16 * 10 * 32) return;
    int lane = idx & 31;
    int ks   = (idx >> 5) % 10;
    int ct   = idx / 320;
    int g = lane >> 2, q = lane & 3;
    int tap = ks >> 1, cb = (ks & 1) * 16;
    int co0 = ct * 16 + g, co1 = co0 + 8;
    int t0 = co0 >> 6, c0 = co0 & 63;
    int t1 = co1 >> 6, c1 = co1 & 63;
    float sc0 = P.gamma[t0][c0] * rsqrtf(P.var[t0][c0] + BN_EPS);
    float sc1 = P.gamma[t1][c1] * rsqrtf(P.var[t1][c1] + BN_EPS);
    int ciA = cb + 2 * q, ciB = cb + 2 * q + 8;
    uint4 v;
    v.x = h2pack(P.w[t0][(c0 * 32 + ciA) * 5 + tap] * sc0,
                 P.w[t0][(c0 * 32 + ciA + 1) * 5 + tap] * sc0);
    v.y = h2pack(P.w[t1][(c1 * 32 + ciA) * 5 + tap] * sc1,
                 P.w[t1][(c1 * 32 + ciA + 1) * 5 + tap] * sc1);
    v.z = h2pack(P.w[t0][(c0 * 32 + ciB) * 5 + tap] * sc0,
                 P.w[t0][(c0 * 32 + ciB + 1) * 5 + tap] * sc0);
    v.w = h2pack(P.w[t1][(c1 * 32 + ciB) * 5 + tap] * sc1,
                 P.w[t1][(c1 * 32 + ciB + 1) * 5 + tap] * sc1);
    g_whf[idx] = v;
}

// ---------------------------------------------------------------------------
// Conv via fp16 mma m16n8k16. grid (4,16,16); 512 threads = 16 warps.
// W A-fragments read DIRECTLY from global (L2/L1-resident 80 KB table);
// only the x slice is staged in smem (8704 B).
// ---------------------------------------------------------------------------
__global__ void __launch_bounds__(512, 1) conv_mma_kernel(ConvParams P) {
    extern __shared__ float sm[];
    uint2* Xh = (uint2*)sm;                    // 1088 uint2 = 8704 B

    const int nc = blockIdx.x;
    const int h  = blockIdx.y;
    const int b  = blockIdx.z;
    const int tid = threadIdx.x;
    const int lane = tid & 31, wp = tid >> 5;
    const int g = lane >> 2, q = lane & 3;
    const int w0 = nc * 128;

    for (int i = tid; i < 1088; i += 512) {
        int q2 = i & 3, oc = i >> 2;
        int o = oc / 136, col = oc - o * 136;
        int wg = w0 - 2 + col;
        uint2 word = make_uint2(0u, 0u);
        if (wg >= 0 && wg < 512) {
            int ciA = 16 * o + 2 * q2;
            const float* xp = P.x + (size_t)((b * 32 + ciA) * 16 + h) * 512 + wg;
            const size_t rs = 16 * 512;
            word.x = h2pack(xp[0], xp[rs]);
            word.y = h2pack(xp[8 * rs], xp[9 * rs]);
        }
        Xh[i] = word;
    }
    __syncthreads();

    float O[16][4];
#pragma unroll
    for (int j = 0; j < 16; j++)
#pragma unroll
        for (int u = 0; u < 4; u++) O[j][u] = 0.0f;

    const uint4* Wg = g_whf + wp * 10 * 32 + lane;
#pragma unroll
    for (int ks = 0; ks < 10; ks++) {
        int tap = ks >> 1, o = ks & 1;
        uint4 A = __ldg(Wg + ks * 32);
        unsigned a[4] = { A.x, A.y, A.z, A.w };
        const uint2* bp = Xh + ((o * 136) + g + tap) * 4 + q;
#pragma unroll
        for (int j = 0; j < 16; j++) {
            uint2 bb = bp[j * 32];
            mma16h(O[j], a, bb.x, bb.y);
        }
    }

    const int co0 = wp * 16 + g;
    const int t0 = co0 >> 6, c0 = co0 & 63;
    const int c1 = (co0 + 8) & 63;
    float sA = P.gamma[t0][c0] * rsqrtf(P.var[t0][c0] + BN_EPS);
    float shift0 = P.beta[t0][c0] - P.mean[t0][c0] * sA;
    float sB = P.gamma[t0][c1] * rsqrtf(P.var[t0][c1] + BN_EPS);
    float shift1 = P.beta[t0][c1] - P.mean[t0][c1] * sB;

    float* r0 = g_qkvp + (size_t)(((t0 * 16 + b) * 64 + c0) * 16 + h) * 512 + w0 + 2 * q;
    float* r1 = g_qkvp + (size_t)(((t0 * 16 + b) * 64 + c1) * 16 + h) * 512 + w0 + 2 * q;
#pragma unroll
    for (int j = 0; j < 16; j++) {
        float v0 = O[j][0] + shift0, v1 = O[j][1] + shift0;
        float v2 = O[j][2] + shift1, v3 = O[j][3] + shift1;
        v0 = (v0 >= 0.0f) ? v0 : LRELU_SLOPE * v0;
        v1 = (v1 >= 0.0f) ? v1 : LRELU_SLOPE * v1;
        v2 = (v2 >= 0.0f) ? v2 : LRELU_SLOPE * v2;
        v3 = (v3 >= 0.0f) ? v3 : LRELU_SLOPE * v3;
        *(float2*)(r0 + j * 8) = make_float2(v0, v1);
        *(float2*)(r1 + j * 8) = make_float2(v2, v3);
    }
}

// ---------------------------------------------------------------------------
// Attention per (b,c): EXACT R12 kernel (258.8us baseline).
// Phase A tf32 mma (warp tile m64 x n32), max-free exp2 softmax,
// Phase B f16 mma m16n8k16 with k-permutation. 1024 CTAs, 512 thr, 152064 B.
// ---------------------------------------------------------------------------
__global__ void __launch_bounds__(512, 1) attn_kernel(float* __restrict__ out) {
    extern __shared__ float sm[];
    float2*   Qf2 = (float2*)sm;                  // 4096 f2 (tf32 frag pairs)
    float2*   Kf2 = Qf2 + 4096;                   // 4096 f2
    unsigned* Vh  = (unsigned*)(Kf2 + 4096);      // 4096 half2 words
    unsigned* Ph  = Vh + 4096;                    // 16384 half2 words
    float*    redP = (float*)(Ph + 16384);        // 64*17
    float*    redI = redP + 64 * 17;              // 64

    const int bc   = blockIdx.x;
    const int tid  = threadIdx.x;
    const int lane = tid & 31, wp = tid >> 5;
    const int g = lane >> 2, q = lane & 3;

    // ---- Staging ----
    {
        const float* qg = g_qkvp + (size_t)(0 * 1024 + bc) * 8192;
        const float* kg = g_qkvp + (size_t)(1 * 1024 + bc) * 8192;
        const int w = tid & 511;
#pragma unroll
        for (int j = 0; j < 8; j++) {
            int ks = j >> 2, qq = j & 3;
            int h0 = ks * 8 + qq;
            float a0 = qg[h0 * 512 + w] * LOG2E;
            float a1 = qg[(h0 + 4) * 512 + w] * LOG2E;
            Qf2[ks * 2048 + Fidx(w, qq)] = make_float2(to_tf32(a0), to_tf32(a1));
            float k0 = kg[h0 * 512 + w];
            float k1 = kg[(h0 + 4) * 512 + w];
            Kf2[ks * 2048 + Fidx(w, qq)] = make_float2(to_tf32(k0), to_tf32(k1));
        }
        const float* vg = g_qkvp + (size_t)(2 * 1024 + bc) * 8192;
#pragma unroll
        for (int it = 0; it < 8; it++) {
            int idx = tid + it * 512;
            int oh = idx & 1, qs2 = (idx >> 1) & 3, hh = (idx >> 3) & 15, kb = idx >> 7;
            int cc = kb * 16 + oh * 8 + qs2;
            Vh[idx] = h2pack(vg[hh * 512 + cc], vg[hh * 512 + cc + 4]);
        }
    }
    __syncthreads();

    const int nbA   = wp * 32;
    const int rbase = (g & 3) + 8 * (g >> 2);
    const int qs    = g & 3, hb = g >> 2;

    const int gbA = nbA + g;
    const float2* kE = Kf2 + gbA * 4 + (q ^ ((gbA >> 2) & 3));
    const float2* kO = Kf2 + (gbA + 8) * 4 + (q ^ (((gbA + 8) >> 2) & 3));

    float O[4][4];
#pragma unroll
    for (int t = 0; t < 4; t++)
#pragma unroll
        for (int u = 0; u < 4; u++) O[t][u] = 0.0f;

    for (int blk = 0; blk < 8; blk++) {
        float L[4][4][4];
#pragma unroll
        for (int mt = 0; mt < 4; mt++)
#pragma unroll
            for (int j = 0; j < 4; j++)
#pragma unroll
                for (int u = 0; u < 4; u++) L[mt][j][u] = 0.0f;

#pragma unroll
        for (int ks = 0; ks < 2; ks++) {
            float2 B0 = kE[ks * 2048];
            float2 B1 = kO[ks * 2048];
            float2 B2 = kE[ks * 2048 + 64];
            float2 B3 = kO[ks * 2048 + 64];
            unsigned b0x = __float_as_uint(B0.x), b0y = __float_as_uint(B0.y);
            unsigned b1x = __float_as_uint(B1.x), b1y = __float_as_uint(B1.y);
            unsigned b2x = __float_as_uint(B2.x), b2y = __float_as_uint(B2.y);
            unsigned b3x = __float_as_uint(B3.x), b3y = __float_as_uint(B3.y);
#pragma unroll
            for (int mt = 0; mt < 4; mt++) {
                int W1 = blk * 64 + mt * 16 + rbase;
                float2 p0 = Qf2[ks * 2048 + Fidx(W1, q)];
                float2 p1 = Qf2[ks * 2048 + Fidx(W1 + 4, q)];
                unsigned a[4] = { __float_as_uint(p0.x), __float_as_uint(p1.x),
                                  __float_as_uint(p0.y), __float_as_uint(p1.y) };
                mma8(L[mt][0], a, b0x, b0y);
                mma8(L[mt][1], a, b1x, b1y);
                mma8(L[mt][2], a, b2x, b2y);
                mma8(L[mt][3], a, b3x, b3y);
            }
        }

        float sAr[4], sBr[4];
#pragma unroll
        for (int mt = 0; mt < 4; mt++) {
            float pa = 0.0f, pb = 0.0f;
#pragma unroll
            for (int j = 0; j < 4; j++) {
                float e0 = ex2(L[mt][j][0]); L[mt][j][0] = e0;
                float e1 = ex2(L[mt][j][1]); L[mt][j][1] = e1; pa += e0 + e1;
                float e2 = ex2(L[mt][j][2]); L[mt][j][2] = e2;
                float e3 = ex2(L[mt][j][3]); L[mt][j][3] = e3; pb += e2 + e3;
            }
            pa += __shfl_xor_sync(0xffffffffu, pa, 1);
            pa += __shfl_xor_sync(0xffffffffu, pa, 2);
            pb += __shfl_xor_sync(0xffffffffu, pb, 1);
            pb += __shfl_xor_sync(0xffffffffu, pb, 2);
            sAr[mt] = pa; sBr[mt] = pb;
        }
        if (q == 0) {
#pragma unroll
            for (int mt = 0; mt < 4; mt++) {
                redP[(mt * 16 + rbase) * 17 + wp]     = sAr[mt];
                redP[(mt * 16 + rbase + 4) * 17 + wp] = sBr[mt];
            }
        }
        __syncthreads();
        {
            int row = tid >> 3, jj = tid & 7;
            float s = redP[row * 17 + 2 * jj] + redP[row * 17 + 2 * jj + 1];
            s += __shfl_xor_sync(0xffffffffu, s, 1);
            s += __shfl_xor_sync(0xffffffffu, s, 2);
            s += __shfl_xor_sync(0xffffffffu, s, 4);
            if (jj == 0) redI[row] = __fdividef(1.0f, s);
        }
        __syncthreads();

#pragma unroll
        for (int mt = 0; mt < 4; mt++) {
            float invA = redI[mt * 16 + rbase];
            float invB = redI[mt * 16 + rbase + 4];
#pragma unroll
            for (int j = 0; j < 4; j++) {
#pragma unroll
                for (int c = 0; c < 2; c++) {
                    int col = nbA + j * 8 + 2 * q + c;
                    Ph[(mt * 512 + col) * 8 + ((qs * 2 + hb) ^ (col & 4))] =
                        h2pack(L[mt][j][c] * invA, L[mt][j][c + 2] * invB);
                }
            }
        }
        __syncthreads();

#pragma unroll
        for (int ks = 0; ks < 4; ks++) {
            int kbV = blk * 4 + ks;
            uint2 va = *(const uint2*)(Vh + ((kbV * 16 + g) * 4 + q) * 2);
            uint2 vb = *(const uint2*)(Vh + ((kbV * 16 + g + 8) * 4 + q) * 2);
            unsigned a[4] = { va.x, vb.x, va.y, vb.y };
#pragma unroll
            for (int nt = 0; nt < 4; nt++) {
                int col = wp * 32 + nt * 8 + g;
                uint2 bb = *(const uint2*)(Ph + (ks * 512 + col) * 8 + ((q * 2) ^ (col & 4)));
                mma16h(O[nt], a, bb.x, bb.y);
            }
        }
        __syncthreads();
    }

    const float* pe = g_qkvp + (size_t)(3 * 1024 + bc) * 8192;
    float* dst = out + (size_t)bc * 8192;
#pragma unroll
    for (int t = 0; t < 4; t++) {
        int col = wp * 32 + t * 8 + 2 * q;
        float2 pA = *(const float2*)(pe + g * 512 + col);
        float2 pB = *(const float2*)(pe + (g + 8) * 512 + col);
        *(float2*)(dst + g * 512 + col) =
            make_float2(O[t][0] + pA.x, O[t][1] + pA.y);
        *(float2*)(dst + (g + 8) * 512 + col) =
            make_float2(O[t][2] + pB.x, O[t][3] + pB.y);
    }
}

// ---------------------------------------------------------------------------
extern "C" void kernel_launch(void* const* d_in, const int* in_sizes, int n_in,
                              void* d_out, int out_size) {
    (void)in_sizes; (void)n_in; (void)out_size;

    ConvParams P;
    P.x = (const float*)d_in[0];
    for (int i = 0; i < 4; i++) {
        P.w[i]     = (const float*)d_in[1 + i * 5 + 0];
        P.gamma[i] = (const float*)d_in[1 + i * 5 + 1];
        P.beta[i]  = (const float*)d_in[1 + i * 5 + 2];
        P.mean[i]  = (const float*)d_in[1 + i * 5 + 3];
        P.var[i]   = (const float*)d_in[1 + i * 5 + 4];
    }

    const int CONV_SMEM = 1088 * 8;                                      // 8704 B
    const int ATTN_SMEM = 4096 * 8 * 2 + 4096 * 4 + 16384 * 4
                        + (64 * 17) * 4 + 64 * 4;                        // 152064 B
    cudaFuncSetAttribute(conv_mma_kernel, cudaFuncAttributeMaxDynamicSharedMemorySize, CONV_SMEM);
    cudaFuncSetAttribute(attn_kernel, cudaFuncAttributeMaxDynamicSharedMemorySize, ATTN_SMEM);

    prepack_kernel<<<20, 256>>>(P);
    conv_mma_kernel<<<dim3(4, 16, 16), 512, CONV_SMEM>>>(P);
    attn_kernel<<<1024, 512, ATTN_SMEM>>>((float*)d_out);
}